// round 9
// baseline (speedup 1.0000x reference)
#include <cuda_runtime.h>
#include <math.h>
typedef unsigned long long ull;
typedef ulonglong2 ull2;

#define NTH 512
#define TST 1024
#define BATCH 1024
#define EPSF 1e-8f

// ---- SMEM (float offsets) ----
#define W0i   0        // 128*142: interleaved (w10,w20), col j at j*142, k at 2k
#define W1i   18176    // 128*258: interleaved (w11,w21)
#define WOUTo 51200    // 384
#define ACT0  51584    // [70][8]: rows of [xn(6)|h(64)] ; ull-aligned rowpairs
#define SCRA  52144    // [128][8]
#define SCRB  53168    // [128][8]
#define XB    54192    // 48
#define NB    54240    // 8
#define SMF   54248    // 216,992 B

__device__ __forceinline__ ull pack2(float lo, float hi){ull r;asm("mov.b64 %0,{%1,%2};":"=l"(r):"f"(lo),"f"(hi));return r;}
__device__ __forceinline__ void unpack2(ull v,float&lo,float&hi){asm("mov.b64 {%0,%1},%2;":"=f"(lo),"=f"(hi):"l"(v));}
__device__ __forceinline__ void ffma2(ull&d,ull a,ull b){asm("fma.rn.f32x2 %0,%1,%2,%0;":"+l"(d):"l"(a),"l"(b));}
__device__ __forceinline__ ull addx2(ull a,ull b){ull r;asm("add.rn.f32x2 %0,%1,%2;":"=l"(r):"l"(a),"l"(b));return r;}
__device__ __forceinline__ ull mulx2(ull a,ull b){ull r;asm("mul.rn.f32x2 %0,%1,%2;":"=l"(r):"l"(a),"l"(b));return r;}
__device__ __forceinline__ ull shflx(ull v, int m){
    unsigned lo=(unsigned)v, hi=(unsigned)(v>>32);
    lo=__shfl_xor_sync(0xffffffffu,lo,m);
    hi=__shfl_xor_sync(0xffffffffu,hi,m);
    return ((ull)hi<<32)|lo;
}
__device__ __forceinline__ ull sel4(ull a0,ull a1,ull a2,ull a3,int c){
    ull x=(c&1)?a1:a0; ull y=(c&1)?a3:a2; return (c&2)?y:x;
}

__global__ void __launch_bounds__(NTH, 1)
lmsc_kernel(const float* __restrict__ x, const float* __restrict__ initF,
            const float* __restrict__ w10,const float* __restrict__ b10,
            const float* __restrict__ w20,const float* __restrict__ b20,
            const float* __restrict__ w11,const float* __restrict__ b11,
            const float* __restrict__ w21,const float* __restrict__ b21,
            const float* __restrict__ w12,const float* __restrict__ b12,
            const float* __restrict__ w22,const float* __restrict__ b22,
            const float* __restrict__ wa, const float* __restrict__ ba,
            const float* __restrict__ wb, const float* __restrict__ bb,
            const float* __restrict__ wout,float* __restrict__ out)
{
    extern __shared__ float sm[];
    const int tid = threadIdx.x;
    const int b0 = blockIdx.x * 8;
    const int j  = tid >> 2, c  = tid & 3;   // L0/L1: rowpair p=c ; L2: k-quarter
    const int jq = tid >> 3, c8 = tid & 7;   // heads: k-eighth

    // ---- SMEM init ----
    for (int idx = tid; idx < 70*128; idx += NTH) {
        int k = idx >> 7, jj = idx & 127;
        sm[W0i + jj*142 + 2*k]   = w10[idx];
        sm[W0i + jj*142 + 2*k+1] = w20[idx];
    }
    for (int idx = tid; idx < 128*128; idx += NTH) {
        int k = idx >> 7, jj = idx & 127;
        sm[W1i + jj*258 + 2*k]   = w11[idx];
        sm[W1i + jj*258 + 2*k+1] = w21[idx];
    }
    if (tid < 384) sm[WOUTo + tid] = wout[tid];
    if (tid < 512) {
        int r = tid >> 6, jj = tid & 63;
        sm[ACT0 + (6+jj)*8 + r] = initF[(b0+r)*66 + 2 + jj];
    }

    // ---- register state ----
    const ull bz0a = pack2(b10[j], b10[j]);
    const ull bz0b = pack2(b20[j], b20[j]);
    const ull bz1a = pack2(b11[j], b11[j]);
    const ull bz1b = pack2(b21[j], b21[j]);
    const ull bz2a = (c==0) ? pack2(b12[j], b12[j]) : 0ULL;
    const ull bz2b = (c==0) ? pack2(b22[j], b22[j]) : 0ULL;

    float wl2a[32], wl2b[32];
#pragma unroll
    for (int i = 0; i < 32; i++) {
        wl2a[i] = w12[(i*4+c)*128 + j];
        wl2b[i] = w22[(i*4+c)*128 + j];
    }
    const float bav = ba[jq], bbv = bb[jq];
    const float* wap = wa + jq;     // element k at wap[k*64]
    const float* wbp = wb + jq;

    // ---- x prologue ----
    const int xr = tid / 6, xd = tid - 6*xr;
    float xc = 0.f;
    if (tid < 48) sm[XB + tid] = x[((size_t)(b0+xr)*TST)*6 + xd];
    __syncthreads();
    if (tid < 8) {
        float s = 0.f;
#pragma unroll
        for (int d = 0; d < 6; d++){ float v = sm[XB + tid*6 + d]; s = fmaf(v,v,s); }
        float nrm = sqrtf(s); sm[NB + tid] = nrm;
        float inv = 1.0f/(nrm + EPSF);
#pragma unroll
        for (int d = 0; d < 6; d++) sm[ACT0 + d*8 + tid] = sm[XB + tid*6 + d]*inv;
    }
    if (tid < 48) xc = x[((size_t)(b0+xr)*TST + 1)*6 + xd];

    float* outs = out;
    float* alph = out + (size_t)BATCH*TST*6;

#pragma unroll 1
    for (int t = 0; t < TST; t++) {
        __syncthreads();                               // A: x/h/norm ready

        {   // L0: (j, rowpair c), full K=70, both mats, no exchange
            const float* wp = sm + W0i + j*142;
            const float* ap = sm + ACT0 + 2*c;
            ull a1 = bz0a, a2 = bz0b;
#pragma unroll 14
            for (int k = 0; k < 70; k++) {
                ull av = *(const ull*)(ap + k*8);
                ull wv = *(const ull*)(wp + 2*k);      // (w1,w2)
                float w1f, w2f; unpack2(wv, w1f, w2f);
                ffma2(a1, av, pack2(w1f, w1f));
                ffma2(a2, av, pack2(w2f, w2f));
            }
            float x1a,x1b,x2a,x2b;
            unpack2(a1,x1a,x1b); unpack2(a2,x2a,x2b);
            *(ull*)(sm + SCRA + j*8 + 2*c) =
                pack2(tanhf(x1a)*tanhf(x2a), tanhf(x1b)*tanhf(x2b));
        }
        __syncthreads();                               // B

        {   // L1: (j, rowpair c), full K=128, both mats
            const float* wp = sm + W1i + j*258;
            const float* ap = sm + SCRA + 2*c;
            ull a1 = bz1a, a2 = bz1b;
#pragma unroll 16
            for (int k = 0; k < 128; k++) {
                ull av = *(const ull*)(ap + k*8);
                ull wv = *(const ull*)(wp + 2*k);
                float w1f, w2f; unpack2(wv, w1f, w2f);
                ffma2(a1, av, pack2(w1f, w1f));
                ffma2(a2, av, pack2(w2f, w2f));
            }
            float x1a,x1b,x2a,x2b;
            unpack2(a1,x1a,x1b); unpack2(a2,x2a,x2b);
            *(ull*)(sm + SCRB + j*8 + 2*c) =
                pack2(tanhf(x1a)*tanhf(x2a), tanhf(x1b)*tanhf(x2b));
        }
        __syncthreads();                               // C

        {   // L2: (j, k-quarter c), reg weights, 8 rows; 2-level shuffle combine
            ull m0=bz2a,m1=bz2a,m2=bz2a,m3=bz2a, n0=bz2b,n1=bz2b,n2=bz2b,n3=bz2b;
#pragma unroll 8
            for (int i = 0; i < 32; i++) {
                const float* bp = sm + SCRB + (i*4+c)*8;
                ull2 qa = *(const ull2*)(bp);
                ull2 qb = *(const ull2*)(bp + 4);
                ull w1d = pack2(wl2a[i], wl2a[i]);
                ull w2d = pack2(wl2b[i], wl2b[i]);
                ffma2(m0,qa.x,w1d); ffma2(m1,qa.y,w1d); ffma2(m2,qb.x,w1d); ffma2(m3,qb.y,w1d);
                ffma2(n0,qa.x,w2d); ffma2(n1,qa.y,w2d); ffma2(n2,qb.x,w2d); ffma2(n3,qb.y,w2d);
            }
#pragma unroll
            for (int lv = 1; lv <= 2; lv <<= 1) {
                m0=addx2(m0,shflx(m0,lv)); m1=addx2(m1,shflx(m1,lv));
                m2=addx2(m2,shflx(m2,lv)); m3=addx2(m3,shflx(m3,lv));
                n0=addx2(n0,shflx(n0,lv)); n1=addx2(n1,shflx(n1,lv));
                n2=addx2(n2,shflx(n2,lv)); n3=addx2(n3,shflx(n3,lv));
            }
            ull v = mulx2(sel4(m0,m1,m2,m3,c), sel4(n0,n1,n2,n3,c));
            float g0,g1; unpack2(v,g0,g1);
            *(ull*)(sm + SCRA + j*8 + 2*c) = pack2(tanhf(g0), tanhf(g1));
        }
        __syncthreads();                               // D

        {   // heads: (jq, k-eighth c8), weights via __ldg; 3-level shuffle combine
            ull A0=0,A1=0,A2=0,A3=0,B0=0,B1=0,B2=0,B3=0;
#pragma unroll 8
            for (int i = 0; i < 16; i++) {
                const int kk = i*8 + c8;
                float va = __ldg(wap + kk*64);
                float vb = __ldg(wbp + kk*64);
                const float* gp = sm + SCRA + kk*8;
                ull2 qa = *(const ull2*)(gp);
                ull2 qb = *(const ull2*)(gp + 4);
                ull wad = pack2(va,va), wbd = pack2(vb,vb);
                ffma2(A0,qa.x,wad); ffma2(A1,qa.y,wad); ffma2(A2,qb.x,wad); ffma2(A3,qb.y,wad);
                ffma2(B0,qa.x,wbd); ffma2(B1,qa.y,wbd); ffma2(B2,qb.x,wbd); ffma2(B3,qb.y,wbd);
            }
#pragma unroll
            for (int lv = 1; lv <= 4; lv <<= 1) {
                A0=addx2(A0,shflx(A0,lv)); A1=addx2(A1,shflx(A1,lv));
                A2=addx2(A2,shflx(A2,lv)); A3=addx2(A3,shflx(A3,lv));
                B0=addx2(B0,shflx(B0,lv)); B1=addx2(B1,shflx(B1,lv));
                B2=addx2(B2,shflx(B2,lv)); B3=addx2(B3,shflx(B3,lv));
            }
            if (c8 < 4) {
                const int p = c8;
                ull ua = sel4(A0,A1,A2,A3,p), ub = sel4(B0,B1,B2,B3,p);
                float pa0,pa1,pb0,pb1; unpack2(ua,pa0,pa1); unpack2(ub,pb0,pb1);
                float al0 = expf(pa0 + bav), al1 = expf(pa1 + bav);
                float be0 = tanhf(pb0 + bbv), be1 = tanhf(pb1 + bbv);
                const int hoff = ACT0 + (6+jq)*8 + 2*p;
                ull hv = *(const ull*)(sm + hoff);
                float h0,h1; unpack2(hv,h0,h1);
                float hn0 = fmaf(expf(-al0*sm[NB+2*p]),   h0-be0, be0);
                float hn1 = fmaf(expf(-al1*sm[NB+2*p+1]), h1-be1, be1);
                *(ull*)(sm + hoff) = pack2(hn0,hn1);
                alph[((size_t)(b0+2*p)*TST + t)*64 + jq]   = al0;
                alph[((size_t)(b0+2*p+1)*TST + t)*64 + jq] = al1;
            }
            if (tid < 48 && t+1 < TST) sm[XB + tid] = xc;   // stage x(t+1)
        }
        __syncthreads();                               // E

        if (tid < 48) {   // outs = h @ wout; prefetch x(t+2)
            const int r = tid/6, o = tid - 6*r;
            float acc = 0.f;
#pragma unroll
            for (int k = 0; k < 64; k++)
                acc = fmaf(sm[ACT0 + (6+k)*8 + r], sm[WOUTo + k*6 + o], acc);
            outs[((size_t)(b0+r)*TST + t)*6 + o] = acc;
            if (t+2 < TST) xc = x[((size_t)(b0+xr)*TST + (t+2))*6 + xd];
        }
        if (tid < 8 && t+1 < TST) {   // norm + xn for t+1
            float s = 0.f;
#pragma unroll
            for (int d = 0; d < 6; d++){ float v = sm[XB + tid*6 + d]; s = fmaf(v,v,s); }
            float nrm = sqrtf(s); sm[NB + tid] = nrm;
            float inv = 1.0f/(nrm + EPSF);
#pragma unroll
            for (int d = 0; d < 6; d++) sm[ACT0 + d*8 + tid] = sm[XB + tid*6 + d]*inv;
        }
    }
}

extern "C" void kernel_launch(void* const* d_in, const int* in_sizes, int n_in,
                              void* d_out, int out_size)
{
    const float* x    =(const float*)d_in[0];  const float* initF=(const float*)d_in[1];
    const float* w10  =(const float*)d_in[2];  const float* b10  =(const float*)d_in[3];
    const float* w20  =(const float*)d_in[4];  const float* b20  =(const float*)d_in[5];
    const float* w11  =(const float*)d_in[6];  const float* b11  =(const float*)d_in[7];
    const float* w21  =(const float*)d_in[8];  const float* b21  =(const float*)d_in[9];
    const float* w12  =(const float*)d_in[10]; const float* b12  =(const float*)d_in[11];
    const float* w22  =(const float*)d_in[12]; const float* b22  =(const float*)d_in[13];
    const float* wa   =(const float*)d_in[14]; const float* ba   =(const float*)d_in[15];
    const float* wb   =(const float*)d_in[16]; const float* bb   =(const float*)d_in[17];
    const float* wout =(const float*)d_in[18];
    float* out = (float*)d_out;

    const int smem_bytes = SMF * 4;
    cudaFuncSetAttribute(lmsc_kernel, cudaFuncAttributeMaxDynamicSharedMemorySize, smem_bytes);
    lmsc_kernel<<<BATCH/8, NTH, smem_bytes>>>(x, initF, w10,b10,w20,b20, w11,b11,w21,b21,
                                              w12,b12,w22,b22, wa,ba,wb,bb, wout, out);
}

// round 13
// speedup vs baseline: 1.8897x; 1.8897x over previous
#include <cuda_runtime.h>
#include <math.h>
typedef unsigned long long ull;
typedef ulonglong2 ull2;

#define NTH 256
#define TST 1024
#define BATCH 1024
#define EPSF 1e-8f

// ---- SMEM layout (float offsets) — R4's, unchanged ----
#define W10O 0
#define W20O 9088
#define W11O 18176
#define W21O 34688
#define WOUTO 51200
#define BA    51584
#define BB    51648
#define C0P   51712   // 70*8  [xn(6)|h(64)], word f*8+r
#define CBD   52272   // 128*8 : L0 gate out; REUSED for L2 gate out
#define CB2   53296   // 128*8 : L1 gate out
#define STGO  54320   // heads partials compact g*512 + p*128 + jh*2 + e
#define XB    56368
#define NB    56416
#define SMF   56424   // 225,696 B

__device__ __forceinline__ ull pack2(float lo, float hi){ull r;asm("mov.b64 %0,{%1,%2};":"=l"(r):"f"(lo),"f"(hi));return r;}
__device__ __forceinline__ void unpack2(ull v,float&lo,float&hi){asm("mov.b64 {%0,%1},%2;":"=f"(lo),"=f"(hi):"l"(v));}
__device__ __forceinline__ void ffma2(ull&d,ull a,ull b){asm("fma.rn.f32x2 %0,%1,%2,%0;":"+l"(d):"l"(a),"l"(b));}
__device__ __forceinline__ ull addx2(ull a,ull b){ull r;asm("add.rn.f32x2 %0,%1,%2;":"=l"(r):"l"(a),"l"(b));return r;}
__device__ __forceinline__ ull mulx2(ull a,ull b){ull r;asm("mul.rn.f32x2 %0,%1,%2;":"=l"(r):"l"(a),"l"(b));return r;}
__device__ __forceinline__ ull shflx1(ull v, int m){
    unsigned lo=(unsigned)v, hi=(unsigned)(v>>32);
    lo=__shfl_xor_sync(0xffffffffu,lo,m);
    hi=__shfl_xor_sync(0xffffffffu,hi,m);
    return ((ull)hi<<32)|lo;
}
__device__ __forceinline__ ull tanh2p(ull v){
    float a,b; unpack2(v,a,b);
    return pack2(tanhf(a), tanhf(b));
}

// R4-proven fused layer (verbatim)
template<int K, int UNR>
__device__ __forceinline__ void layer_fused(float (&g)[4], const float* __restrict__ actp,
                                            const float* __restrict__ wp1,
                                            const float* __restrict__ wp2, ull binit)
{
    ull a0=binit, a1=binit, a2=binit, a3=binit;
#pragma unroll UNR
    for (int k = 0; k < K; k++) {
        const float4 q = *(const float4*)(actp + k*8);
        const ull w = pack2(wp1[k], wp2[k]);
        ffma2(a0, pack2(q.x,q.x), w);
        ffma2(a1, pack2(q.y,q.y), w);
        ffma2(a2, pack2(q.z,q.z), w);
        ffma2(a3, pack2(q.w,q.w), w);
    }
    float x1,x2;
    unpack2(a0,x1,x2); g[0]=tanhf(x1)*tanhf(x2);
    unpack2(a1,x1,x2); g[1]=tanhf(x1)*tanhf(x2);
    unpack2(a2,x1,x2); g[2]=tanhf(x1)*tanhf(x2);
    unpack2(a3,x1,x2); g[3]=tanhf(x1)*tanhf(x2);
}

__global__ void __launch_bounds__(NTH, 1)
lmsc_kernel(const float* __restrict__ x, const float* __restrict__ initF,
            const float* __restrict__ w10,const float* __restrict__ b10,
            const float* __restrict__ w20,const float* __restrict__ b20,
            const float* __restrict__ w11,const float* __restrict__ b11,
            const float* __restrict__ w21,const float* __restrict__ b21,
            const float* __restrict__ w12,const float* __restrict__ b12,
            const float* __restrict__ w22,const float* __restrict__ b22,
            const float* __restrict__ wa, const float* __restrict__ ba,
            const float* __restrict__ wb, const float* __restrict__ bb,
            const float* __restrict__ wout,float* __restrict__ out)
{
    extern __shared__ float sm[];
    const int tid = threadIdx.x;
    const int b0 = blockIdx.x * 8;
    const int rh = tid >> 7, j  = tid & 127;   // L0/L1 (R4)
    const int j2 = tid >> 1, khl = tid & 1;    // NEW: L2 butterfly
    const int hm = tid >> 7;                   // heads (R4): 0->wa, 1->wb
    const int kh = (tid >> 6) & 1;             // heads K-half
    const int jh = tid & 63;                   // heads column

    // ---- SMEM init (R4 verbatim) ----
    for (int idx = tid; idx < 70*128; idx += NTH) {
        int k = idx >> 7, jj = idx & 127;
        sm[W10O + jj*71 + k] = w10[idx];
        sm[W20O + jj*71 + k] = w20[idx];
    }
    for (int idx = tid; idx < 128*128; idx += NTH) {
        int k = idx >> 7, jj = idx & 127;
        sm[W11O + jj*129 + k] = w11[idx];
        sm[W21O + jj*129 + k] = w21[idx];
    }
    for (int idx = tid; idx < 384; idx += NTH) sm[WOUTO + idx] = wout[idx];
    if (tid < 64) { sm[BA + tid] = ba[tid]; sm[BB + tid] = bb[tid]; }
    for (int idx = tid; idx < 512; idx += NTH) {
        int r = idx >> 6, jj = idx & 63;
        sm[C0P + (6+jj)*8 + r] = initF[(b0+r)*66 + 2 + jj];
    }

    // ---- per-thread registers ----
    const ull bp0 = pack2(b10[j], b20[j]);
    const ull bp1 = pack2(b11[j], b21[j]);
    const ull bz2a = khl ? 0ULL : pack2(b12[j2], b12[j2]);   // NEW L2 bias
    const ull bz2b = khl ? 0ULL : pack2(b22[j2], b22[j2]);

    float wl2a[64], wl2b[64];      // NEW: L2 cols, k = 2i+khl
#pragma unroll
    for (int i = 0; i < 64; i++) {
        wl2a[i] = w12[(2*i+khl)*128 + j2];
        wl2b[i] = w22[(2*i+khl)*128 + j2];
    }
    float whd[64];                 // R4 heads weights (verbatim)
    {
        const float* hsrc = hm ? wb : wa;
#pragma unroll
        for (int i = 0; i < 64; i++) whd[i] = hsrc[(kh*64 + i)*64 + jh];
    }

    // ---- x prologue (R4 verbatim) ----
    const int xr = tid / 6, xd = tid - 6*xr;
    float xc = 0.f;
    if (tid < 48) sm[XB + tid] = x[((size_t)(b0+xr)*TST)*6 + xd];
    __syncthreads();
    if (tid < 8) {
        float s = 0.f;
#pragma unroll
        for (int d = 0; d < 6; d++){ float v = sm[XB + tid*6 + d]; s = fmaf(v,v,s); }
        float nrm = sqrtf(s); sm[NB + tid] = nrm;
        float inv = 1.0f/(nrm + EPSF);
#pragma unroll
        for (int d = 0; d < 6; d++) sm[C0P + d*8 + tid] = sm[XB + tid*6 + d]*inv;
    }
    if (tid < 48) xc = x[((size_t)(b0+xr)*TST + 1)*6 + xd];

    float* outs = out;
    float* alph = out + (size_t)BATCH*TST*6;

#pragma unroll 1
    for (int t = 0; t < TST; t++) {
        __syncthreads();                         // A

        {   // L0 (R4 verbatim) -> CBD
            float g[4];
            layer_fused<70,14>(g, sm + C0P + rh*4, sm + W10O + j*71, sm + W20O + j*71, bp0);
            *(float4*)(sm + CBD + j*8 + rh*4) = make_float4(g[0],g[1],g[2],g[3]);
        }
        __syncthreads();                         // B

        {   // L1 (R4 verbatim) -> CB2
            float g[4];
            layer_fused<128,16>(g, sm + CBD + rh*4, sm + W11O + j*129, sm + W21O + j*129, bp1);
            *(float4*)(sm + CB2 + j*8 + rh*4) = make_float4(g[0],g[1],g[2],g[3]);
        }
        __syncthreads();                         // C

        {   // NEW L2 butterfly: (j2, khl), k=2i+khl, both mats, 8 rows; gate -> CBD
            ull m0=bz2a,m1=bz2a,m2=bz2a,m3=bz2a, n0=bz2b,n1=bz2b,n2=bz2b,n3=bz2b;
#pragma unroll
            for (int i = 0; i < 64; i++) {
                const float* bp = sm + CB2 + (2*i+khl)*8;
                ull2 qa = *(const ull2*)(bp);       // rows 0-3
                ull2 qb = *(const ull2*)(bp + 4);   // rows 4-7
                ull w1 = pack2(wl2a[i], wl2a[i]);
                ull w2 = pack2(wl2b[i], wl2b[i]);
                ffma2(m0,qa.x,w1); ffma2(m1,qa.y,w1); ffma2(m2,qb.x,w1); ffma2(m3,qb.y,w1);
                ffma2(n0,qa.x,w2); ffma2(n1,qa.y,w2); ffma2(n2,qb.x,w2); ffma2(n3,qb.y,w2);
            }
            m0=addx2(m0,shflx1(m0,1)); m1=addx2(m1,shflx1(m1,1));
            m2=addx2(m2,shflx1(m2,1)); m3=addx2(m3,shflx1(m3,1));
            n0=addx2(n0,shflx1(n0,1)); n1=addx2(n1,shflx1(n1,1));
            n2=addx2(n2,shflx1(n2,1)); n3=addx2(n3,shflx1(n3,1));
            ull ga = khl ? tanh2p(mulx2(m2,n2)) : tanh2p(mulx2(m0,n0));
            ull gb = khl ? tanh2p(mulx2(m3,n3)) : tanh2p(mulx2(m1,n1));
            *(ull2*)(sm + CBD + j2*8 + 4*khl) = make_ulonglong2(ga, gb);
        }
        __syncthreads();                         // D

        {   // heads (R4 verbatim, source = CBD): split-K, reg weights -> STGO compact
            const float* actH = sm + CBD + kh*512;
            ull a0 = 0, a1 = 0, a2 = 0, a3 = 0;
#pragma unroll
            for (int i = 0; i < 64; i++) {
                ull2 u0 = *(const ull2*)(actH + i*8);
                ull2 u1 = *(const ull2*)(actH + i*8 + 4);
                ull w = pack2(whd[i], whd[i]);
                ffma2(a0, u0.x, w); ffma2(a1, u0.y, w);
                ffma2(a2, u1.x, w); ffma2(a3, u1.y, w);
            }
            const int g = hm*2 + kh;
            *(ull*)(sm + STGO + g*512 + 0*128 + jh*2) = a0;
            *(ull*)(sm + STGO + g*512 + 1*128 + jh*2) = a1;
            *(ull*)(sm + STGO + g*512 + 2*128 + jh*2) = a2;
            *(ull*)(sm + STGO + g*512 + 3*128 + jh*2) = a3;
        }
        __syncthreads();                         // E

        {   // combine (R4 verbatim): alpha/beta, h update, alpha out; stage x(t+1)
            const int jj = tid & 63;
            const int rg = tid >> 6;
#pragma unroll
            for (int rr = 0; rr < 2; rr++) {
                const int r = rg*2 + rr;
                float pa = sm[STGO + 0*512 + rg*128 + jj*2 + rr]
                         + sm[STGO + 1*512 + rg*128 + jj*2 + rr];
                float pb = sm[STGO + 2*512 + rg*128 + jj*2 + rr]
                         + sm[STGO + 3*512 + rg*128 + jj*2 + rr];
                float alpha = expf(pa + sm[BA + jj]);
                float beta  = tanhf(pb + sm[BB + jj]);
                float hold  = sm[C0P + (6+jj)*8 + r];
                float hn = fmaf(expf(-alpha*sm[NB + r]), hold - beta, beta);
                sm[C0P + (6+jj)*8 + r] = hn;
                alph[((size_t)(b0+r)*TST + t)*64 + jj] = alpha;
            }
            if (tid < 48 && t+1 < TST) sm[XB + tid] = xc;
        }
        __syncthreads();                         // F

        if (tid < 48) {   // wout (R4 verbatim); prefetch x(t+2)
            const int r = tid/6, o = tid - 6*r;
            float acc = 0.f;
#pragma unroll
            for (int k = 0; k < 64; k++)
                acc = fmaf(sm[C0P + (6+k)*8 + r], sm[WOUTO + k*6 + o], acc);
            outs[((size_t)(b0+r)*TST + t)*6 + o] = acc;
            if (t+2 < TST) xc = x[((size_t)(b0+xr)*TST + (t+2))*6 + xd];
        }
        if (tid < 8) {    // norm + xn for t+1 (R4 verbatim)
            float s = 0.f;
#pragma unroll
            for (int d = 0; d < 6; d++){ float v = sm[XB + tid*6 + d]; s = fmaf(v,v,s); }
            float nrm = sqrtf(s); sm[NB + tid] = nrm;
            float inv = 1.0f/(nrm + EPSF);
#pragma unroll
            for (int d = 0; d < 6; d++) sm[C0P + d*8 + tid] = sm[XB + tid*6 + d]*inv;
        }
    }
}

extern "C" void kernel_launch(void* const* d_in, const int* in_sizes, int n_in,
                              void* d_out, int out_size)
{
    const float* x    =(const float*)d_in[0];  const float* initF=(const float*)d_in[1];
    const float* w10  =(const float*)d_in[2];  const float* b10  =(const float*)d_in[3];
    const float* w20  =(const float*)d_in[4];  const float* b20  =(const float*)d_in[5];
    const float* w11  =(const float*)d_in[6];  const float* b11  =(const float*)d_in[7];
    const float* w21  =(const float*)d_in[8];  const float* b21  =(const float*)d_in[9];
    const float* w12  =(const float*)d_in[10]; const float* b12  =(const float*)d_in[11];
    const float* w22  =(const float*)d_in[12]; const float* b22  =(const float*)d_in[13];
    const float* wa   =(const float*)d_in[14]; const float* ba   =(const float*)d_in[15];
    const float* wb   =(const float*)d_in[16]; const float* bb   =(const float*)d_in[17];
    const float* wout =(const float*)d_in[18];
    float* out = (float*)d_out;

    const int smem_bytes = SMF * 4;
    cudaFuncSetAttribute(lmsc_kernel, cudaFuncAttributeMaxDynamicSharedMemorySize, smem_bytes);
    lmsc_kernel<<<BATCH/8, NTH, smem_bytes>>>(x, initF, w10,b10,w20,b20, w11,b11,w21,b21,
                                              w12,b12,w22,b22, wa,ba,wb,bb, wout, out);
}

// round 14
// speedup vs baseline: 1.9734x; 1.0443x over previous
#include <cuda_runtime.h>
#include <math.h>
typedef unsigned long long ull;
typedef ulonglong2 ull2;

#define NTH 256
#define TST 1024
#define BATCH 1024
#define EPSF 1e-8f

// ---- SMEM layout (float offsets) ----
// W10O/W20O: col-major stride 70 : w[j*70+k]   (6j+khl spans banks; conflict-free)
// W11O/W21O: col-major stride 130: w[j*130+k]  (2j+khl spans banks)
// C0P [70][8] acts [xn(6)|h(64)]; CBD/CB2 [128][8]; STGO heads partials (R4)
#define W10O 0        // 8960
#define W20O 8960     // 8960
#define W11O 17920    // 16640
#define W21O 34560    // 16640
#define WOUTO 51200   // 384
#define BA    51584
#define BB    51648
#define C0P   51712   // 560
#define CBD   52272   // 1024 : L0 gate out; reused for L2 gate out
#define CB2   53296   // 1024 : L1 gate out
#define STGO  54320   // 2048 : heads partials g*512 + p*128 + jh*2 + e
#define XB    56368
#define NB    56416
#define SMF   56424   // 225,696 B

__device__ __forceinline__ ull pack2(float lo, float hi){ull r;asm("mov.b64 %0,{%1,%2};":"=l"(r):"f"(lo),"f"(hi));return r;}
__device__ __forceinline__ void unpack2(ull v,float&lo,float&hi){asm("mov.b64 {%0,%1},%2;":"=f"(lo),"=f"(hi):"l"(v));}
__device__ __forceinline__ void ffma2(ull&d,ull a,ull b){asm("fma.rn.f32x2 %0,%1,%2,%0;":"+l"(d):"l"(a),"l"(b));}
__device__ __forceinline__ ull addx2(ull a,ull b){ull r;asm("add.rn.f32x2 %0,%1,%2;":"=l"(r):"l"(a),"l"(b));return r;}
__device__ __forceinline__ ull mulx2(ull a,ull b){ull r;asm("mul.rn.f32x2 %0,%1,%2;":"=l"(r):"l"(a),"l"(b));return r;}
__device__ __forceinline__ ull shflx1(ull v, int m){
    unsigned lo=(unsigned)v, hi=(unsigned)(v>>32);
    lo=__shfl_xor_sync(0xffffffffu,lo,m);
    hi=__shfl_xor_sync(0xffffffffu,hi,m);
    return ((ull)hi<<32)|lo;
}
__device__ __forceinline__ ull tanh2p(ull v){
    float a,b; unpack2(v,a,b);
    return pack2(tanhf(a), tanhf(b));
}

__global__ void __launch_bounds__(NTH, 1)
lmsc_kernel(const float* __restrict__ x, const float* __restrict__ initF,
            const float* __restrict__ w10,const float* __restrict__ b10,
            const float* __restrict__ w20,const float* __restrict__ b20,
            const float* __restrict__ w11,const float* __restrict__ b11,
            const float* __restrict__ w21,const float* __restrict__ b21,
            const float* __restrict__ w12,const float* __restrict__ b12,
            const float* __restrict__ w22,const float* __restrict__ b22,
            const float* __restrict__ wa, const float* __restrict__ ba,
            const float* __restrict__ wb, const float* __restrict__ bb,
            const float* __restrict__ wout,float* __restrict__ out)
{
    extern __shared__ float sm[];
    const int tid = threadIdx.x;
    const int b0 = blockIdx.x * 8;
    const int j2 = tid >> 1, khl = tid & 1;   // L0/L1/L2 butterfly mapping (PROVEN)
    const int hm = tid >> 7;                  // heads (R4): 0->wa, 1->wb
    const int kh = (tid >> 6) & 1;            // heads K-half
    const int jh = tid & 63;                  // heads column

    // ---- SMEM init ----
    for (int idx = tid; idx < 70*128; idx += NTH) {
        int k = idx >> 7, jj = idx & 127;
        sm[W10O + jj*70 + k] = w10[idx];
        sm[W20O + jj*70 + k] = w20[idx];
    }
    for (int idx = tid; idx < 128*128; idx += NTH) {
        int k = idx >> 7, jj = idx & 127;
        sm[W11O + jj*130 + k] = w11[idx];
        sm[W21O + jj*130 + k] = w21[idx];
    }
    for (int idx = tid; idx < 384; idx += NTH) sm[WOUTO + idx] = wout[idx];
    if (tid < 64) { sm[BA + tid] = ba[tid]; sm[BB + tid] = bb[tid]; }
    for (int idx = tid; idx < 512; idx += NTH) {
        int r = idx >> 6, jj = idx & 63;
        sm[C0P + (6+jj)*8 + r] = initF[(b0+r)*66 + 2 + jj];
    }

    // ---- per-thread registers ----
    const ull bz0a = khl ? 0ULL : pack2(b10[j2], b10[j2]);
    const ull bz0b = khl ? 0ULL : pack2(b20[j2], b20[j2]);
    const ull bz1a = khl ? 0ULL : pack2(b11[j2], b11[j2]);
    const ull bz1b = khl ? 0ULL : pack2(b21[j2], b21[j2]);
    const ull bz2a = khl ? 0ULL : pack2(b12[j2], b12[j2]);
    const ull bz2b = khl ? 0ULL : pack2(b22[j2], b22[j2]);

    float wl2a[64], wl2b[64];      // L2 cols, k = 2i+khl (PROVEN in R12)
#pragma unroll
    for (int i = 0; i < 64; i++) {
        wl2a[i] = w12[(2*i+khl)*128 + j2];
        wl2b[i] = w22[(2*i+khl)*128 + j2];
    }
    float whd[64];                 // R4 heads weights (verbatim)
    {
        const float* hsrc = hm ? wb : wa;
#pragma unroll
        for (int i = 0; i < 64; i++) whd[i] = hsrc[(kh*64 + i)*64 + jh];
    }

    // ---- x prologue (R4 verbatim) ----
    const int xr = tid / 6, xd = tid - 6*xr;
    float xc = 0.f;
    if (tid < 48) sm[XB + tid] = x[((size_t)(b0+xr)*TST)*6 + xd];
    __syncthreads();
    if (tid < 8) {
        float s = 0.f;
#pragma unroll
        for (int d = 0; d < 6; d++){ float v = sm[XB + tid*6 + d]; s = fmaf(v,v,s); }
        float nrm = sqrtf(s); sm[NB + tid] = nrm;
        float inv = 1.0f/(nrm + EPSF);
#pragma unroll
        for (int d = 0; d < 6; d++) sm[C0P + d*8 + tid] = sm[XB + tid*6 + d]*inv;
    }
    if (tid < 48) xc = x[((size_t)(b0+xr)*TST + 1)*6 + xd];

    float* outs = out;
    float* alph = out + (size_t)BATCH*TST*6;

#pragma unroll 1
    for (int t = 0; t < TST; t++) {
        __syncthreads();                         // A: x/h/norm ready

        {   // L0 butterfly: (j2, khl), k=2i+khl<70, SMEM weights stride 70, 8 rows
            const float* w1p = sm + W10O + j2*70 + khl;
            const float* w2p = sm + W20O + j2*70 + khl;
            ull m0=bz0a,m1=bz0a,m2=bz0a,m3=bz0a, n0=bz0b,n1=bz0b,n2=bz0b,n3=bz0b;
#pragma unroll 7
            for (int i = 0; i < 35; i++) {
                const float* ap = sm + C0P + (2*i+khl)*8;
                ull2 qa = *(const ull2*)(ap);       // rows 0-3
                ull2 qb = *(const ull2*)(ap + 4);   // rows 4-7
                float w1f = w1p[2*i], w2f = w2p[2*i];
                ull w1 = pack2(w1f,w1f), w2 = pack2(w2f,w2f);
                ffma2(m0,qa.x,w1); ffma2(m1,qa.y,w1); ffma2(m2,qb.x,w1); ffma2(m3,qb.y,w1);
                ffma2(n0,qa.x,w2); ffma2(n1,qa.y,w2); ffma2(n2,qb.x,w2); ffma2(n3,qb.y,w2);
            }
            m0=addx2(m0,shflx1(m0,1)); m1=addx2(m1,shflx1(m1,1));
            m2=addx2(m2,shflx1(m2,1)); m3=addx2(m3,shflx1(m3,1));
            n0=addx2(n0,shflx1(n0,1)); n1=addx2(n1,shflx1(n1,1));
            n2=addx2(n2,shflx1(n2,1)); n3=addx2(n3,shflx1(n3,1));
            ull ga = khl ? mulx2(tanh2p(m2), tanh2p(n2)) : mulx2(tanh2p(m0), tanh2p(n0));
            ull gb = khl ? mulx2(tanh2p(m3), tanh2p(n3)) : mulx2(tanh2p(m1), tanh2p(n1));
            *(ull2*)(sm + CBD + j2*8 + 4*khl) = make_ulonglong2(ga, gb);
        }
        __syncthreads();                         // B

        {   // L1 butterfly: (j2, khl), k=2i+khl<128, SMEM weights stride 130, 8 rows
            const float* w1p = sm + W11O + j2*130 + khl;
            const float* w2p = sm + W21O + j2*130 + khl;
            ull m0=bz1a,m1=bz1a,m2=bz1a,m3=bz1a, n0=bz1b,n1=bz1b,n2=bz1b,n3=bz1b;
#pragma unroll 16
            for (int i = 0; i < 64; i++) {
                const float* ap = sm + CBD + (2*i+khl)*8;
                ull2 qa = *(const ull2*)(ap);
                ull2 qb = *(const ull2*)(ap + 4);
                float w1f = w1p[2*i], w2f = w2p[2*i];
                ull w1 = pack2(w1f,w1f), w2 = pack2(w2f,w2f);
                ffma2(m0,qa.x,w1); ffma2(m1,qa.y,w1); ffma2(m2,qb.x,w1); ffma2(m3,qb.y,w1);
                ffma2(n0,qa.x,w2); ffma2(n1,qa.y,w2); ffma2(n2,qb.x,w2); ffma2(n3,qb.y,w2);
            }
            m0=addx2(m0,shflx1(m0,1)); m1=addx2(m1,shflx1(m1,1));
            m2=addx2(m2,shflx1(m2,1)); m3=addx2(m3,shflx1(m3,1));
            n0=addx2(n0,shflx1(n0,1)); n1=addx2(n1,shflx1(n1,1));
            n2=addx2(n2,shflx1(n2,1)); n3=addx2(n3,shflx1(n3,1));
            ull ga = khl ? mulx2(tanh2p(m2), tanh2p(n2)) : mulx2(tanh2p(m0), tanh2p(n0));
            ull gb = khl ? mulx2(tanh2p(m3), tanh2p(n3)) : mulx2(tanh2p(m1), tanh2p(n1));
            *(ull2*)(sm + CB2 + j2*8 + 4*khl) = make_ulonglong2(ga, gb);
        }
        __syncthreads();                         // C

        {   // L2 butterfly (R12 verbatim): reg weights, gate tanh(x1*x2) -> CBD
            ull m0=bz2a,m1=bz2a,m2=bz2a,m3=bz2a, n0=bz2b,n1=bz2b,n2=bz2b,n3=bz2b;
#pragma unroll
            for (int i = 0; i < 64; i++) {
                const float* bp = sm + CB2 + (2*i+khl)*8;
                ull2 qa = *(const ull2*)(bp);
                ull2 qb = *(const ull2*)(bp + 4);
                ull w1 = pack2(wl2a[i], wl2a[i]);
                ull w2 = pack2(wl2b[i], wl2b[i]);
                ffma2(m0,qa.x,w1); ffma2(m1,qa.y,w1); ffma2(m2,qb.x,w1); ffma2(m3,qb.y,w1);
                ffma2(n0,qa.x,w2); ffma2(n1,qa.y,w2); ffma2(n2,qb.x,w2); ffma2(n3,qb.y,w2);
            }
            m0=addx2(m0,shflx1(m0,1)); m1=addx2(m1,shflx1(m1,1));
            m2=addx2(m2,shflx1(m2,1)); m3=addx2(m3,shflx1(m3,1));
            n0=addx2(n0,shflx1(n0,1)); n1=addx2(n1,shflx1(n1,1));
            n2=addx2(n2,shflx1(n2,1)); n3=addx2(n3,shflx1(n3,1));
            ull ga = khl ? tanh2p(mulx2(m2,n2)) : tanh2p(mulx2(m0,n0));
            ull gb = khl ? tanh2p(mulx2(m3,n3)) : tanh2p(mulx2(m1,n1));
            *(ull2*)(sm + CBD + j2*8 + 4*khl) = make_ulonglong2(ga, gb);
        }
        __syncthreads();                         // D

        {   // heads (R4/R12 verbatim): split-K, reg weights -> STGO compact
            const float* actH = sm + CBD + kh*512;
            ull a0 = 0, a1 = 0, a2 = 0, a3 = 0;
#pragma unroll
            for (int i = 0; i < 64; i++) {
                ull2 u0 = *(const ull2*)(actH + i*8);
                ull2 u1 = *(const ull2*)(actH + i*8 + 4);
                ull w = pack2(whd[i], whd[i]);
                ffma2(a0, u0.x, w); ffma2(a1, u0.y, w);
                ffma2(a2, u1.x, w); ffma2(a3, u1.y, w);
            }
            const int g = hm*2 + kh;
            *(ull*)(sm + STGO + g*512 + 0*128 + jh*2) = a0;
            *(ull*)(sm + STGO + g*512 + 1*128 + jh*2) = a1;
            *(ull*)(sm + STGO + g*512 + 2*128 + jh*2) = a2;
            *(ull*)(sm + STGO + g*512 + 3*128 + jh*2) = a3;
        }
        __syncthreads();                         // E

        {   // combine (R4/R12 verbatim): alpha/beta, h update, alpha out; stage x(t+1)
            const int jj = tid & 63;
            const int rg = tid >> 6;
#pragma unroll
            for (int rr = 0; rr < 2; rr++) {
                const int r = rg*2 + rr;
                float pa = sm[STGO + 0*512 + rg*128 + jj*2 + rr]
                         + sm[STGO + 1*512 + rg*128 + jj*2 + rr];
                float pb = sm[STGO + 2*512 + rg*128 + jj*2 + rr]
                         + sm[STGO + 3*512 + rg*128 + jj*2 + rr];
                float alpha = expf(pa + sm[BA + jj]);
                float beta  = tanhf(pb + sm[BB + jj]);
                float hold  = sm[C0P + (6+jj)*8 + r];
                float hn = fmaf(expf(-alpha*sm[NB + r]), hold - beta, beta);
                sm[C0P + (6+jj)*8 + r] = hn;
                alph[((size_t)(b0+r)*TST + t)*64 + jj] = alpha;
            }
            if (tid < 48 && t+1 < TST) sm[XB + tid] = xc;
        }
        __syncthreads();                         // F

        if (tid < 48) {   // wout (R4 verbatim); prefetch x(t+2)
            const int r = tid/6, o = tid - 6*r;
            float acc = 0.f;
#pragma unroll
            for (int k = 0; k < 64; k++)
                acc = fmaf(sm[C0P + (6+k)*8 + r], sm[WOUTO + k*6 + o], acc);
            outs[((size_t)(b0+r)*TST + t)*6 + o] = acc;
            if (t+2 < TST) xc = x[((size_t)(b0+xr)*TST + (t+2))*6 + xd];
        }
        if (tid < 8) {    // norm + xn for t+1 (R4 verbatim)
            float s = 0.f;
#pragma unroll
            for (int d = 0; d < 6; d++){ float v = sm[XB + tid*6 + d]; s = fmaf(v,v,s); }
            float nrm = sqrtf(s); sm[NB + tid] = nrm;
            float inv = 1.0f/(nrm + EPSF);
#pragma unroll
            for (int d = 0; d < 6; d++) sm[C0P + d*8 + tid] = sm[XB + tid*6 + d]*inv;
        }
    }
}

extern "C" void kernel_launch(void* const* d_in, const int* in_sizes, int n_in,
                              void* d_out, int out_size)
{
    const float* x    =(const float*)d_in[0];  const float* initF=(const float*)d_in[1];
    const float* w10  =(const float*)d_in[2];  const float* b10  =(const float*)d_in[3];
    const float* w20  =(const float*)d_in[4];  const float* b20  =(const float*)d_in[5];
    const float* w11  =(const float*)d_in[6];  const float* b11  =(const float*)d_in[7];
    const float* w21  =(const float*)d_in[8];  const float* b21  =(const float*)d_in[9];
    const float* w12  =(const float*)d_in[10]; const float* b12  =(const float*)d_in[11];
    const float* w22  =(const float*)d_in[12]; const float* b22  =(const float*)d_in[13];
    const float* wa   =(const float*)d_in[14]; const float* ba   =(const float*)d_in[15];
    const float* wb   =(const float*)d_in[16]; const float* bb   =(const float*)d_in[17];
    const float* wout =(const float*)d_in[18];
    float* out = (float*)d_out;

    const int smem_bytes = SMF * 4;
    cudaFuncSetAttribute(lmsc_kernel, cudaFuncAttributeMaxDynamicSharedMemorySize, smem_bytes);
    lmsc_kernel<<<BATCH/8, NTH, smem_bytes>>>(x, initF, w10,b10,w20,b20, w11,b11,w21,b21,
                                              w12,b12,w22,b22, wa,ba,wb,bb, wout, out);
}